// round 14
// baseline (speedup 1.0000x reference)
#include <cuda_runtime.h>
#include <cuda_bf16.h>
#include <math.h>
#include <stdint.h>

#define NN   50000
#define NE   500000
#define IND  64
#define ED   16
#define HID  256
#define NH   4
#define NL   4
#define NG   64
#define BN_EPS 1e-5f

#define RT_TILES 391                 // ceil(NN/128)
#define PAD_ROWS (RT_TILES * 128)    // 50048

// ---------------- scratch (static __device__ arrays; no allocation) ----------------
__device__ __align__(16) float g_x[(size_t)NN * HID];     // current node features
__device__ __align__(16) float g_kv[(size_t)NN * 512];    // k|v per node (gathered)
__device__ __align__(16) float g_qs[(size_t)NN * 512];    // q|skip per node (streamed)
__device__ __align__(16) float g_attn[(size_t)NN * HID];  // post-attention features
__device__ __align__(16) float g_qe[(size_t)NN * 64];     // per-node We_h q_h (16 per head)
__device__ float g_qbe[NN * NH];                          // per-node q_h . be_h
__device__ float g_stats[2 * HID];
__device__ float g_pool[NG * HID];
__device__ float g_cnt[NG];
// CSR by destination
__device__ int  g_deg[NN];
__device__ int  g_rowptr[NN + 1];
__device__ int  g_cursor[NN];
__device__ __align__(8) int2 g_adj[NE];
// bf16-split GEMM operands (layer GEMMs)
__device__ __align__(16) __nv_bfloat16 g_ahi[(size_t)PAD_ROWS * HID];
__device__ __align__(16) __nv_bfloat16 g_alo[(size_t)PAD_ROWS * HID];
__device__ __align__(16) __nv_bfloat16 g_whi[(size_t)NL * 4 * HID * HID]; // W^T: [l][w][n][k]
__device__ __align__(16) __nv_bfloat16 g_wlo[(size_t)NL * 4 * HID * HID];
// projection operands (K=64)
__device__ __align__(16) __nv_bfloat16 g_phi[(size_t)PAD_ROWS * IND];
__device__ __align__(16) __nv_bfloat16 g_plo[(size_t)PAD_ROWS * IND];
__device__ __align__(16) __nv_bfloat16 g_pwhi[HID * IND];  // proj_W^T: [n][k]
__device__ __align__(16) __nv_bfloat16 g_pwlo[HID * IND];

// ================= CSR build =================
__global__ void __launch_bounds__(256) clear_deg_kernel()
{
    int i = blockIdx.x * 256 + threadIdx.x;
    if (i < NN) g_deg[i] = 0;
}
__global__ void __launch_bounds__(256) hist_kernel(const int* __restrict__ ei)
{
    int i = blockIdx.x * 256 + threadIdx.x;
    if (i < NE) atomicAdd(&g_deg[ei[NE + i]], 1);
}
#define SCAN_T 1024
#define SCAN_ITEMS ((NN + SCAN_T - 1) / SCAN_T)
__global__ void __launch_bounds__(SCAN_T) scan_kernel()
{
    __shared__ int wsum[32];
    int t = threadIdx.x;
    int lo = t * SCAN_ITEMS;
    int hi = min(lo + SCAN_ITEMS, NN);
    int s = 0;
    for (int i = lo; i < hi; i++) s += g_deg[i];
    int lane = t & 31, w = t >> 5;
    int v = s;
#pragma unroll
    for (int o = 1; o < 32; o <<= 1) {
        int u = __shfl_up_sync(0xffffffffu, v, o);
        if (lane >= o) v += u;
    }
    if (lane == 31) wsum[w] = v;
    __syncthreads();
    if (w == 0) {
        int x = wsum[lane];
#pragma unroll
        for (int o = 1; o < 32; o <<= 1) {
            int u = __shfl_up_sync(0xffffffffu, x, o);
            if (lane >= o) x += u;
        }
        wsum[lane] = x;
    }
    __syncthreads();
    int excl = v - s + (w ? wsum[w - 1] : 0);
    int run = excl;
    for (int i = lo; i < hi; i++) {
        g_rowptr[i] = run;
        g_cursor[i] = run;
        run += g_deg[i];
    }
    if (t == SCAN_T - 1) g_rowptr[NN] = excl + s;
}
__global__ void __launch_bounds__(256) scatter_kernel(const int* __restrict__ ei)
{
    int i = blockIdx.x * 256 + threadIdx.x;
    if (i < NE) {
        int dst = ei[NE + i];
        int pos = atomicAdd(&g_cursor[dst], 1);
        g_adj[pos] = make_int2(ei[i], i);
    }
}

// ================= misc clears =================
__global__ void __launch_bounds__(512) clear_stats_kernel() { g_stats[threadIdx.x] = 0.f; }
__global__ void __launch_bounds__(256) clear_pool_kernel()
{
    int i = blockIdx.x * 256 + threadIdx.x;
    if (i < NG * HID) g_pool[i] = 0.f;
    if (i < NG) g_cnt[i] = 0.f;
}

// ================= weight prep (layer GEMMs) =================
__global__ void __launch_bounds__(256) convert_w_kernel(
    const float* __restrict__ Wq, const float* __restrict__ Wk,
    const float* __restrict__ Wv, const float* __restrict__ Wskip)
{
    int idx = blockIdx.x * 256 + threadIdx.x;
    int k = idx & 255;
    int n = (idx >> 8) & 255;
    int w = (idx >> 16) & 3;
    int l = idx >> 18;
    const float* W = (w == 0) ? Wq : (w == 1) ? Wk : (w == 2) ? Wv : Wskip;
    float val = W[((size_t)l * 256 + k) * 256 + n];
    __nv_bfloat16 hi = __float2bfloat16(val);
    __nv_bfloat16 lo = __float2bfloat16(val - __bfloat162float(hi));
    g_whi[idx] = hi;
    g_wlo[idx] = lo;
}

// ================= projection prep =================
__global__ void __launch_bounds__(256) convert_nf_kernel(const float* __restrict__ nf)
{
    size_t idx = (size_t)blockIdx.x * 256 + threadIdx.x;   // over PAD_ROWS*64
    int r = (int)(idx >> 6);
    float val = (r < NN) ? nf[idx] : 0.f;
    __nv_bfloat16 hi = __float2bfloat16(val);
    __nv_bfloat16 lo = __float2bfloat16(val - __bfloat162float(hi));
    g_phi[idx] = hi;
    g_plo[idx] = lo;
}
__global__ void __launch_bounds__(256) convert_pw_kernel(const float* __restrict__ pW)
{
    int idx = blockIdx.x * 256 + threadIdx.x;   // over 256*64, output [n][k]
    int k = idx & 63;
    int n = idx >> 6;
    float val = pW[(size_t)k * HID + n];
    __nv_bfloat16 hi = __float2bfloat16(val);
    __nv_bfloat16 lo = __float2bfloat16(val - __bfloat162float(hi));
    g_pwhi[idx] = hi;
    g_pwlo[idx] = lo;
}

// ================= mma.sync bf16 GEMM (layer) =================
#define APAD 72
#define ASMEM_ELEMS (128 * APAD)
#define BSMEM_ELEMS (256 * APAD)

__device__ __forceinline__ void mma16816(float* c, const uint32_t* a, uint32_t b0, uint32_t b1) {
    asm volatile("mma.sync.aligned.m16n8k16.row.col.f32.bf16.bf16.f32 "
                 "{%0,%1,%2,%3}, {%4,%5,%6,%7}, {%8,%9}, {%0,%1,%2,%3};"
                 : "+f"(c[0]), "+f"(c[1]), "+f"(c[2]), "+f"(c[3])
                 : "r"(a[0]), "r"(a[1]), "r"(a[2]), "r"(a[3]), "r"(b0), "r"(b1));
}

__global__ void __launch_bounds__(256, 1) mmagemm_kernel(
    int l, const float* __restrict__ b0p, const float* __restrict__ b1p,
    const float* __restrict__ b2p, const float* __restrict__ b3p)
{
    extern __shared__ __align__(16) __nv_bfloat16 sm[];
    __nv_bfloat16* sA = sm;
    __nv_bfloat16* sB = sm + ASMEM_ELEMS;

    const int tid  = threadIdx.x;
    const int lane = tid & 31;
    const int wid  = tid >> 5;
    const int gid  = lane >> 2;
    const int tig  = lane & 3;
    const int rt   = blockIdx.x;
    const int w    = blockIdx.y;
    const int m0   = (wid >> 2) * 64;
    const int n0   = (wid & 3) * 64;

    float acc[4][8][4];
#pragma unroll
    for (int i = 0; i < 4; i++)
#pragma unroll
        for (int j = 0; j < 8; j++)
#pragma unroll
            for (int t = 0; t < 4; t++) acc[i][j][t] = 0.f;

    const size_t aoff = (size_t)rt * 128 * HID;
    const size_t boff = (size_t)(l * 4 + w) * HID * HID;

#pragma unroll 1
    for (int pass = 0; pass < 3; pass++) {
        const __nv_bfloat16* Ag = ((pass == 1) ? g_alo : g_ahi) + aoff;
        const __nv_bfloat16* Bg = ((pass == 2) ? g_wlo : g_whi) + boff;
#pragma unroll 1
        for (int kt = 0; kt < 4; kt++) {
            const int kbase = kt * 64;
            __syncthreads();
#pragma unroll
            for (int it = 0; it < 4; it++) {
                int e = tid + it * 256;
                int row = e >> 3, kg = e & 7;
                uint4 v = *(const uint4*)(Ag + (size_t)row * HID + kbase + kg * 8);
                *(uint4*)(sA + row * APAD + kg * 8) = v;
            }
#pragma unroll
            for (int it = 0; it < 8; it++) {
                int e = tid + it * 256;
                int row = e >> 3, kg = e & 7;
                uint4 v = *(const uint4*)(Bg + (size_t)row * HID + kbase + kg * 8);
                *(uint4*)(sB + row * APAD + kg * 8) = v;
            }
            __syncthreads();

#pragma unroll
            for (int kk = 0; kk < 4; kk++) {
                const int k0 = kk * 16;
                uint32_t af[4][4];
#pragma unroll
                for (int i = 0; i < 4; i++) {
                    const __nv_bfloat16* base = sA + (m0 + i * 16 + gid) * APAD + k0 + 2 * tig;
                    af[i][0] = *(const uint32_t*)(base);
                    af[i][1] = *(const uint32_t*)(base + 8 * APAD);
                    af[i][2] = *(const uint32_t*)(base + 8);
                    af[i][3] = *(const uint32_t*)(base + 8 * APAD + 8);
                }
#pragma unroll
                for (int j = 0; j < 8; j++) {
                    const __nv_bfloat16* bb = sB + (n0 + j * 8 + gid) * APAD + k0 + 2 * tig;
                    uint32_t b0 = *(const uint32_t*)(bb);
                    uint32_t b1 = *(const uint32_t*)(bb + 8);
#pragma unroll
                    for (int i = 0; i < 4; i++)
                        mma16816(acc[i][j], af[i], b0, b1);
                }
            }
        }
    }

    const float* bias = (w == 0) ? b0p : (w == 1) ? b1p : (w == 2) ? b2p : b3p;
    float* dstbase = (w == 0) ? g_qs : (w == 1) ? g_kv : (w == 2) ? g_kv : g_qs;
    const int coff = (w == 0 || w == 1) ? 0 : 256;
#pragma unroll
    for (int i = 0; i < 4; i++) {
        int node0 = rt * 128 + m0 + i * 16 + gid;
#pragma unroll
        for (int j = 0; j < 8; j++) {
            int col = n0 + j * 8 + 2 * tig;
            float2 bv = *(const float2*)(bias + col);
            if (node0 < NN) {
                float2 st = make_float2(acc[i][j][0] + bv.x, acc[i][j][1] + bv.y);
                *(float2*)(dstbase + (size_t)node0 * 512 + coff + col) = st;
            }
            int node1 = node0 + 8;
            if (node1 < NN) {
                float2 st = make_float2(acc[i][j][2] + bv.x, acc[i][j][3] + bv.y);
                *(float2*)(dstbase + (size_t)node1 * 512 + coff + col) = st;
            }
        }
    }
}

// ================= projection mma GEMM: g_x = nf @ proj_W + b; also writes bf16 split =================
// grid (391); block tile 128m x 256n, K=64 (single tile), 3 passes.
__global__ void __launch_bounds__(256, 1) projmma_kernel(const float* __restrict__ bias)
{
    extern __shared__ __align__(16) __nv_bfloat16 sm[];
    __nv_bfloat16* sA = sm;                   // [128][APAD], first 64 cols used
    __nv_bfloat16* sB = sm + ASMEM_ELEMS;     // [256][APAD]

    const int tid  = threadIdx.x;
    const int lane = tid & 31;
    const int wid  = tid >> 5;
    const int gid  = lane >> 2;
    const int tig  = lane & 3;
    const int rt   = blockIdx.x;
    const int m0   = (wid >> 2) * 64;
    const int n0   = (wid & 3) * 64;

    float acc[4][8][4];
#pragma unroll
    for (int i = 0; i < 4; i++)
#pragma unroll
        for (int j = 0; j < 8; j++)
#pragma unroll
            for (int t = 0; t < 4; t++) acc[i][j][t] = 0.f;

    const size_t aoff = (size_t)rt * 128 * IND;

#pragma unroll 1
    for (int pass = 0; pass < 3; pass++) {
        const __nv_bfloat16* Ag = ((pass == 1) ? g_plo : g_phi) + aoff;
        const __nv_bfloat16* Bg = (pass == 2) ? g_pwlo : g_pwhi;
        __syncthreads();
        // A: 128 rows x 64 bf16 = 1024 uint4
#pragma unroll
        for (int it = 0; it < 4; it++) {
            int e = tid + it * 256;
            int row = e >> 3, kg = e & 7;
            uint4 v = *(const uint4*)(Ag + (size_t)row * IND + kg * 8);
            *(uint4*)(sA + row * APAD + kg * 8) = v;
        }
        // B: 256 rows x 64 bf16 = 2048 uint4
#pragma unroll
        for (int it = 0; it < 8; it++) {
            int e = tid + it * 256;
            int row = e >> 3, kg = e & 7;
            uint4 v = *(const uint4*)(Bg + (size_t)row * IND + kg * 8);
            *(uint4*)(sB + row * APAD + kg * 8) = v;
        }
        __syncthreads();

#pragma unroll
        for (int kk = 0; kk < 4; kk++) {
            const int k0 = kk * 16;
            uint32_t af[4][4];
#pragma unroll
            for (int i = 0; i < 4; i++) {
                const __nv_bfloat16* base = sA + (m0 + i * 16 + gid) * APAD + k0 + 2 * tig;
                af[i][0] = *(const uint32_t*)(base);
                af[i][1] = *(const uint32_t*)(base + 8 * APAD);
                af[i][2] = *(const uint32_t*)(base + 8);
                af[i][3] = *(const uint32_t*)(base + 8 * APAD + 8);
            }
#pragma unroll
            for (int j = 0; j < 8; j++) {
                const __nv_bfloat16* bb = sB + (n0 + j * 8 + gid) * APAD + k0 + 2 * tig;
                uint32_t b0 = *(const uint32_t*)(bb);
                uint32_t b1 = *(const uint32_t*)(bb + 8);
#pragma unroll
                for (int i = 0; i < 4; i++)
                    mma16816(acc[i][j], af[i], b0, b1);
            }
        }
    }

    // epilogue: g_x = acc + bias; also write bf16 hi/lo split for layer-0 GEMM input
#pragma unroll
    for (int i = 0; i < 4; i++) {
        int node0 = rt * 128 + m0 + i * 16 + gid;
#pragma unroll
        for (int j = 0; j < 8; j++) {
            int col = n0 + j * 8 + 2 * tig;
            float2 bv = *(const float2*)(bias + col);
#pragma unroll
            for (int half = 0; half < 2; half++) {
                int node = node0 + half * 8;
                if (node < NN) {
                    float v0 = acc[i][j][2 * half + 0] + bv.x;
                    float v1 = acc[i][j][2 * half + 1] + bv.y;
                    size_t idx = (size_t)node * HID + col;
                    *(float2*)(g_x + idx) = make_float2(v0, v1);
                    __nv_bfloat16 h0 = __float2bfloat16(v0);
                    __nv_bfloat16 h1 = __float2bfloat16(v1);
                    g_ahi[idx]     = h0;
                    g_ahi[idx + 1] = h1;
                    g_alo[idx]     = __float2bfloat16(v0 - __bfloat162float(h0));
                    g_alo[idx + 1] = __float2bfloat16(v1 - __bfloat162float(h1));
                }
            }
        }
    }
}

// ================= qe precompute =================
__global__ void __launch_bounds__(256) qe_kernel(
    const float* __restrict__ We, const float* __restrict__ be)
{
    __shared__ __align__(16) float sWe[ED][HID];
    __shared__ float sbe[HID];
    for (int i = threadIdx.x; i < ED * HID; i += 256)
        sWe[i >> 8][i & 255] = We[i];
    if (threadIdx.x < HID) sbe[threadIdx.x] = be[threadIdx.x];
    __syncthreads();

    int n = blockIdx.x * 8 + (threadIdx.x >> 5);
    if (n >= NN) return;
    const int lane = threadIdx.x & 31;
    const int t = lane & 7;
    const int c0 = lane * 8;

    const float4* qp = (const float4*)(g_qs + (size_t)n * 512 + c0);
    float4 q0 = qp[0], q1 = qp[1];

    float qe0 = 0.f, qe1 = 0.f, qbe;
#pragma unroll
    for (int f = 0; f < ED; f++) {
        const float4* wp = (const float4*)(&sWe[f][c0]);
        float4 w0 = wp[0], w1 = wp[1];
        float p = q0.x * w0.x + q0.y * w0.y + q0.z * w0.z + q0.w * w0.w
                + q1.x * w1.x + q1.y * w1.y + q1.z * w1.z + q1.w * w1.w;
        p += __shfl_xor_sync(0xffffffffu, p, 1, 8);
        p += __shfl_xor_sync(0xffffffffu, p, 2, 8);
        p += __shfl_xor_sync(0xffffffffu, p, 4, 8);
        if (f == 2 * t)     qe0 = p;
        if (f == 2 * t + 1) qe1 = p;
    }
    {
        const float4* bp = (const float4*)(&sbe[c0]);
        float4 b0 = bp[0], b1 = bp[1];
        float p = q0.x * b0.x + q0.y * b0.y + q0.z * b0.z + q0.w * b0.w
                + q1.x * b1.x + q1.y * b1.y + q1.z * b1.z + q1.w * b1.w;
        p += __shfl_xor_sync(0xffffffffu, p, 1, 8);
        p += __shfl_xor_sync(0xffffffffu, p, 2, 8);
        p += __shfl_xor_sync(0xffffffffu, p, 4, 8);
        qbe = p;
    }
    *(float2*)(g_qe + (size_t)n * 64 + 2 * lane) = make_float2(qe0, qe1);
    if (t == 0) g_qbe[n * NH + (lane >> 3)] = qbe;
}

// ================= fused attention (R12 winner, unchanged) =================
__global__ void __launch_bounds__(256) attn_kernel(
    const float* __restrict__ eattr, const float* __restrict__ We,
    const float* __restrict__ be, const float* __restrict__ Wb)
{
    __shared__ float sbe[HID];
    __shared__ float sWb1[HID];                    // Wb0 + Wb2
    __shared__ float sWb2[HID];                    // Wb1 - Wb2

    if (threadIdx.x < HID) {
        int c = threadIdx.x;
        sbe[c] = be[c];
        float w2 = Wb[2 * HID + c];
        sWb1[c] = Wb[c] + w2;
        sWb2[c] = Wb[HID + c] - w2;
    }
    __syncthreads();

    int n = blockIdx.x * 8 + (threadIdx.x >> 5);
    if (n >= NN) return;
    const int lane = threadIdx.x & 31;
    const int t    = lane & 7;
    const int c0   = lane * 8;

    const float4* qp = (const float4*)(g_qs + (size_t)n * 512 + c0);
    float4 q0 = qp[0], q1 = qp[1];
    float2 qe = *(const float2*)(g_qe + (size_t)n * 64 + 2 * lane);
    float qbe = g_qbe[n * NH + (lane >> 3)];

    float m = -INFINITY, d = 0.f;
    float s0 = 0.f, s1 = 0.f;
    float acc[8] = {0.f,0.f,0.f,0.f,0.f,0.f,0.f,0.f};

    const int beg = g_rowptr[n], end = g_rowptr[n + 1];
    int i = beg;

    for (; i + 2 <= end; i += 2) {
        int2 A = g_adj[i];
        int2 B = g_adj[i + 1];
        const float4* kpa = (const float4*)(g_kv + (size_t)A.x * 512 + c0);
        const float4* vpa = (const float4*)(g_kv + (size_t)A.x * 512 + 256 + c0);
        const float4* kpb = (const float4*)(g_kv + (size_t)B.x * 512 + c0);
        const float4* vpb = (const float4*)(g_kv + (size_t)B.x * 512 + 256 + c0);
        float4 ka0 = kpa[0], ka1 = kpa[1];
        float4 kb0 = kpb[0], kb1 = kpb[1];
        float4 va0 = vpa[0], va1 = vpa[1];
        float4 vb0 = vpb[0], vb1 = vpb[1];
        float2 eaA = *(const float2*)(eattr + (size_t)A.y * ED + 2 * t);
        float2 eaB = *(const float2*)(eattr + (size_t)B.y * ED + 2 * t);

        float pA = q0.x * ka0.x + q0.y * ka0.y + q0.z * ka0.z + q0.w * ka0.w
                 + q1.x * ka1.x + q1.y * ka1.y + q1.z * ka1.z + q1.w * ka1.w
                 + eaA.x * qe.x + eaA.y * qe.y;
        float pB = q0.x * kb0.x + q0.y * kb0.y + q0.z * kb0.z + q0.w * kb0.w
                 + q1.x * kb1.x + q1.y * kb1.y + q1.z * kb1.z + q1.w * kb1.w
                 + eaB.x * qe.x + eaB.y * qe.y;
        pA += __shfl_xor_sync(0xffffffffu, pA, 1, 8);
        pB += __shfl_xor_sync(0xffffffffu, pB, 1, 8);
        pA += __shfl_xor_sync(0xffffffffu, pA, 2, 8);
        pB += __shfl_xor_sync(0xffffffffu, pB, 2, 8);
        pA += __shfl_xor_sync(0xffffffffu, pA, 4, 8);
        pB += __shfl_xor_sync(0xffffffffu, pB, 4, 8);
        float alphaA = (pA + qbe) * 0.125f;
        float alphaB = (pB + qbe) * 0.125f;

        {
            float mn = fmaxf(m, alphaA);
            float sc = __expf(m - mn);
            float w  = __expf(alphaA - mn);
            d  = d  * sc + w;
            s0 = s0 * sc + w * eaA.x;
            s1 = s1 * sc + w * eaA.y;
            acc[0] = acc[0] * sc + w * va0.x;
            acc[1] = acc[1] * sc + w * va0.y;
            acc[2] = acc[2] * sc + w * va0.z;
            acc[3] = acc[3] * sc + w * va0.w;
            acc[4] = acc[4] * sc + w * va1.x;
            acc[5] = acc[5] * sc + w * va1.y;
            acc[6] = acc[6] * sc + w * va1.z;
            acc[7] = acc[7] * sc + w * va1.w;
            m = mn;
        }
        {
            float mn = fmaxf(m, alphaB);
            float sc = __expf(m - mn);
            float w  = __expf(alphaB - mn);
            d  = d  * sc + w;
            s0 = s0 * sc + w * eaB.x;
            s1 = s1 * sc + w * eaB.y;
            acc[0] = acc[0] * sc + w * vb0.x;
            acc[1] = acc[1] * sc + w * vb0.y;
            acc[2] = acc[2] * sc + w * vb0.z;
            acc[3] = acc[3] * sc + w * vb0.w;
            acc[4] = acc[4] * sc + w * vb1.x;
            acc[5] = acc[5] * sc + w * vb1.y;
            acc[6] = acc[6] * sc + w * vb1.z;
            acc[7] = acc[7] * sc + w * vb1.w;
            m = mn;
        }
    }
    if (i < end) {
        int2 A = g_adj[i];
        const float4* kpa = (const float4*)(g_kv + (size_t)A.x * 512 + c0);
        const float4* vpa = (const float4*)(g_kv + (size_t)A.x * 512 + 256 + c0);
        float4 ka0 = kpa[0], ka1 = kpa[1];
        float4 va0 = vpa[0], va1 = vpa[1];
        float2 eaA = *(const float2*)(eattr + (size_t)A.y * ED + 2 * t);

        float pA = q0.x * ka0.x + q0.y * ka0.y + q0.z * ka0.z + q0.w * ka0.w
                 + q1.x * ka1.x + q1.y * ka1.y + q1.z * ka1.z + q1.w * ka1.w
                 + eaA.x * qe.x + eaA.y * qe.y;
        pA += __shfl_xor_sync(0xffffffffu, pA, 1, 8);
        pA += __shfl_xor_sync(0xffffffffu, pA, 2, 8);
        pA += __shfl_xor_sync(0xffffffffu, pA, 4, 8);
        float alphaA = (pA + qbe) * 0.125f;

        float mn = fmaxf(m, alphaA);
        float sc = __expf(m - mn);
        float w  = __expf(alphaA - mn);
        d  = d  * sc + w;
        s0 = s0 * sc + w * eaA.x;
        s1 = s1 * sc + w * eaA.y;
        acc[0] = acc[0] * sc + w * va0.x;
        acc[1] = acc[1] * sc + w * va0.y;
        acc[2] = acc[2] * sc + w * va0.z;
        acc[3] = acc[3] * sc + w * va0.w;
        acc[4] = acc[4] * sc + w * va1.x;
        acc[5] = acc[5] * sc + w * va1.y;
        acc[6] = acc[6] * sc + w * va1.z;
        acc[7] = acc[7] * sc + w * va1.w;
        m = mn;
    }

    float o[8];
#pragma unroll
    for (int j = 0; j < 8; j++) o[j] = acc[j];
#pragma unroll
    for (int f = 0; f < ED; f++) {
        float sv = __shfl_sync(0xffffffffu, (f & 1) ? s1 : s0, f >> 1, 8);
        const float4* wp = (const float4*)(We + f * HID + c0);
        float4 w0 = wp[0], w1 = wp[1];
        o[0] += sv * w0.x; o[1] += sv * w0.y; o[2] += sv * w0.z; o[3] += sv * w0.w;
        o[4] += sv * w1.x; o[5] += sv * w1.y; o[6] += sv * w1.z; o[7] += sv * w1.w;
    }
    {
        const float4* bp = (const float4*)(&sbe[c0]);
        float4 b0 = bp[0], b1 = bp[1];
        o[0] += d * b0.x; o[1] += d * b0.y; o[2] += d * b0.z; o[3] += d * b0.w;
        o[4] += d * b1.x; o[5] += d * b1.y; o[6] += d * b1.z; o[7] += d * b1.w;
    }
    float inv = (d > 0.f) ? (1.f / d) : 0.f;
#pragma unroll
    for (int j = 0; j < 8; j++) o[j] *= inv;

    float sk[8];
    {
        const float4* sp = (const float4*)(g_qs + (size_t)n * 512 + 256 + c0);
        float4 s0v = sp[0], s1v = sp[1];
        sk[0]=s0v.x; sk[1]=s0v.y; sk[2]=s0v.z; sk[3]=s0v.w;
        sk[4]=s1v.x; sk[5]=s1v.y; sk[6]=s1v.z; sk[7]=s1v.w;
    }
    float p = 0.f;
#pragma unroll
    for (int j = 0; j < 8; j++) {
        int c = c0 + j;
        p += o[j] * sWb1[c] + sk[j] * sWb2[c];
    }
#pragma unroll
    for (int off = 16; off; off >>= 1) p += __shfl_xor_sync(0xffffffffu, p, off);
    float beta = 1.f / (1.f + __expf(-p));

    float* op = g_attn + (size_t)n * HID + c0;
    float r[8];
#pragma unroll
    for (int j = 0; j < 8; j++) r[j] = beta * sk[j] + (1.f - beta) * o[j];
    *(float4*)(op)     = *(float4*)(r);
    *(float4*)(op + 4) = *(float4*)(r + 4);
}

// ---------------- batchnorm stats ----------------
__global__ void __launch_bounds__(256) bnstats_kernel()
{
    int c = threadIdx.x;
    int r0 = blockIdx.x * 128;
    int r1 = min(r0 + 128, NN);
    float s = 0.f, s2 = 0.f;
    for (int r = r0; r < r1; r++) {
        float v = g_attn[(size_t)r * HID + c];
        s += v; s2 += v * v;
    }
    atomicAdd(&g_stats[c], s);
    atomicAdd(&g_stats[HID + c], s2);
}

// ---------------- batchnorm apply + LeakyReLU + bf16 split ----------------
__global__ void __launch_bounds__(256) bnapply_convert_kernel(
    const float* __restrict__ gamma, const float* __restrict__ bbeta, int do_convert)
{
    size_t idx = (size_t)blockIdx.x * blockDim.x + threadIdx.x;
    if (idx >= (size_t)NN * HID) return;
    int c = (int)(idx & (HID - 1));
    const float invN = 1.f / (float)NN;
    float mu = g_stats[c] * invN;
    float var = g_stats[HID + c] * invN - mu * mu;
    var = fmaxf(var, 0.f);
    float y = (g_attn[idx] - mu) * rsqrtf(var + BN_EPS) * gamma[c] + bbeta[c];
    y = (y >= 0.f) ? y : 0.1f * y;
    g_x[idx] = y;
    if (do_convert) {
        __nv_bfloat16 hi = __float2bfloat16(y);
        __nv_bfloat16 lo = __float2bfloat16(y - __bfloat162float(hi));
        g_ahi[idx] = hi;
        g_alo[idx] = lo;
    }
}

// ---------------- pooling ----------------
__global__ void __launch_bounds__(256) pool_kernel(const int* __restrict__ batch)
{
    int c = threadIdx.x;
    int r0 = blockIdx.x * 128;
    if (r0 >= NN) return;
    int r1 = min(r0 + 128, NN);
    int cur = batch[r0];
    float s = 0.f;
    int run = 0;
    for (int r = r0; r < r1; r++) {
        int b = batch[r];
        if (b != cur) {
            atomicAdd(&g_pool[cur * HID + c], s);
            if (c == 0) atomicAdd(&g_cnt[cur], (float)run);
            s = 0.f; run = 0; cur = b;
        }
        s += g_x[(size_t)r * HID + c];
        run++;
    }
    atomicAdd(&g_pool[cur * HID + c], s);
    if (c == 0) atomicAdd(&g_cnt[cur], (float)run);
}

// ---------------- head ----------------
__global__ void __launch_bounds__(256) head_kernel(
    const float* __restrict__ hW, const float* __restrict__ hb,
    float* __restrict__ out)
{
    __shared__ float red[8];
    int g = blockIdx.x;
    int c = threadIdx.x;
    float s = g_pool[g * HID + c];
    float ct = fmaxf(g_cnt[g], 1.f);
    float p = (s / ct) * hW[c] + s * hW[HID + c];
#pragma unroll
    for (int off = 16; off; off >>= 1) p += __shfl_xor_sync(0xffffffffu, p, off);
    if ((c & 31) == 0) red[c >> 5] = p;
    __syncthreads();
    if (c == 0) {
        float t = 0.f;
#pragma unroll
        for (int i = 0; i < 8; i++) t += red[i];
        out[g] = t + hb[0];
    }
}

// ---------------- host ----------------
#define GEMM_SMEM_BYTES ((128 * 72 + 256 * 72) * 2)

extern "C" void kernel_launch(void* const* d_in, const int* in_sizes, int n_in,
                              void* d_out, int out_size)
{
    const float* node_features = (const float*)d_in[0];
    const int*   edge_index    = (const int*)d_in[1];
    const float* edge_attr     = (const float*)d_in[2];
    const int*   batch         = (const int*)d_in[3];
    const float* proj_W        = (const float*)d_in[4];
    const float* proj_b        = (const float*)d_in[5];
    const float* Wq            = (const float*)d_in[6];
    const float* bq            = (const float*)d_in[7];
    const float* Wk            = (const float*)d_in[8];
    const float* bk            = (const float*)d_in[9];
    const float* Wv            = (const float*)d_in[10];
    const float* bv            = (const float*)d_in[11];
    const float* We            = (const float*)d_in[12];
    const float* be            = (const float*)d_in[13];
    const float* Wskip         = (const float*)d_in[14];
    const float* bskip         = (const float*)d_in[15];
    const float* Wbeta         = (const float*)d_in[16];
    const float* bng           = (const float*)d_in[17];
    const float* bnb           = (const float*)d_in[18];
    const float* headW         = (const float*)d_in[19];
    const float* headb         = (const float*)d_in[20];
    float* out = (float*)d_out;

    cudaFuncSetAttribute(mmagemm_kernel, cudaFuncAttributeMaxDynamicSharedMemorySize, GEMM_SMEM_BYTES);
    cudaFuncSetAttribute(projmma_kernel, cudaFuncAttributeMaxDynamicSharedMemorySize, GEMM_SMEM_BYTES);

    // CSR by dst + weight prep (layer-invariant)
    clear_deg_kernel<<<(NN + 255) / 256, 256>>>();
    hist_kernel<<<(NE + 255) / 256, 256>>>(edge_index);
    scan_kernel<<<1, SCAN_T>>>();
    scatter_kernel<<<(NE + 255) / 256, 256>>>(edge_index);
    convert_w_kernel<<<(NL * 4 * 256 * 256) / 256, 256>>>(Wq, Wk, Wv, Wskip);
    convert_pw_kernel<<<(HID * IND) / 256, 256>>>(proj_W);
    convert_nf_kernel<<<(PAD_ROWS * IND) / 256, 256>>>(node_features);

    // input projection on tensor cores; epilogue writes g_x + bf16 split
    projmma_kernel<<<RT_TILES, 256, GEMM_SMEM_BYTES>>>(proj_b);

    for (int l = 0; l < NL; l++) {
        clear_stats_kernel<<<1, 512>>>();
        mmagemm_kernel<<<dim3(RT_TILES, 4), 256, GEMM_SMEM_BYTES>>>(
            l, bq + l * HID, bk + l * HID, bv + l * HID, bskip + l * HID);
        qe_kernel<<<(NN + 7) / 8, 256>>>(We + (size_t)l * ED * HID, be + l * HID);
        attn_kernel<<<(NN + 7) / 8, 256>>>(edge_attr,
                                           We + (size_t)l * ED * HID,
                                           be + l * HID,
                                           Wbeta + (size_t)l * 3 * HID);
        bnstats_kernel<<<(NN + 127) / 128, 256>>>();
        bnapply_convert_kernel<<<(NN * HID + 255) / 256, 256>>>(
            bng + l * HID, bnb + l * HID, (l < NL - 1) ? 1 : 0);
    }

    clear_pool_kernel<<<(NG * HID + 255) / 256, 256>>>();
    pool_kernel<<<(NN + 127) / 128, 256>>>(batch);
    head_kernel<<<NG, 256>>>(headW, headb, out);
}

// round 15
// speedup vs baseline: 1.4864x; 1.4864x over previous
#include <cuda_runtime.h>
#include <cuda_bf16.h>
#include <math.h>
#include <stdint.h>

#define NN   50000
#define NE   500000
#define IND  64
#define ED   16
#define HID  256
#define NH   4
#define NL   4
#define NG   64
#define BN_EPS 1e-5f

#define RT_TILES 391                 // ceil(NN/128)
#define PAD_ROWS (RT_TILES * 128)    // 50048

// ---------------- scratch (static __device__ arrays; no allocation) ----------------
__device__ __align__(16) float g_x[(size_t)NN * HID];     // current node features
__device__ __align__(16) float g_kv[(size_t)NN * 512];    // k|v per node (gathered)
__device__ __align__(16) float g_qs[(size_t)NN * 512];    // q|skip per node (streamed)
__device__ __align__(16) float g_attn[(size_t)NN * HID];  // post-attention features
__device__ __align__(16) float g_qe[(size_t)NN * 64];     // per-node We_h q_h (16 per head)
__device__ float g_qbe[NN * NH];                          // per-node q_h . be_h
__device__ float g_stats[2 * HID];
__device__ float g_pool[NG * HID];
__device__ float g_cnt[NG];
// CSR by destination
__device__ int  g_deg[NN];
__device__ int  g_rowptr[NN + 1];
__device__ int  g_cursor[NN];
__device__ __align__(8) int2 g_adj[NE];
// bf16-split GEMM operands
__device__ __align__(16) __nv_bfloat16 g_ahi[(size_t)PAD_ROWS * HID];
__device__ __align__(16) __nv_bfloat16 g_alo[(size_t)PAD_ROWS * HID];
__device__ __align__(16) __nv_bfloat16 g_whi[(size_t)NL * 4 * HID * HID]; // W^T: [l][w][n][k]
__device__ __align__(16) __nv_bfloat16 g_wlo[(size_t)NL * 4 * HID * HID];

// ================= CSR build =================
__global__ void __launch_bounds__(256) clear_deg_kernel()
{
    int i = blockIdx.x * 256 + threadIdx.x;
    if (i < NN) g_deg[i] = 0;
}
__global__ void __launch_bounds__(256) hist_kernel(const int* __restrict__ ei)
{
    int i = blockIdx.x * 256 + threadIdx.x;
    if (i < NE) atomicAdd(&g_deg[ei[NE + i]], 1);
}
#define SCAN_T 1024
#define SCAN_ITEMS ((NN + SCAN_T - 1) / SCAN_T)
__global__ void __launch_bounds__(SCAN_T) scan_kernel()
{
    __shared__ int wsum[32];
    int t = threadIdx.x;
    int lo = t * SCAN_ITEMS;
    int hi = min(lo + SCAN_ITEMS, NN);
    int s = 0;
    for (int i = lo; i < hi; i++) s += g_deg[i];
    int lane = t & 31, w = t >> 5;
    int v = s;
#pragma unroll
    for (int o = 1; o < 32; o <<= 1) {
        int u = __shfl_up_sync(0xffffffffu, v, o);
        if (lane >= o) v += u;
    }
    if (lane == 31) wsum[w] = v;
    __syncthreads();
    if (w == 0) {
        int x = wsum[lane];
#pragma unroll
        for (int o = 1; o < 32; o <<= 1) {
            int u = __shfl_up_sync(0xffffffffu, x, o);
            if (lane >= o) x += u;
        }
        wsum[lane] = x;
    }
    __syncthreads();
    int excl = v - s + (w ? wsum[w - 1] : 0);
    int run = excl;
    for (int i = lo; i < hi; i++) {
        g_rowptr[i] = run;
        g_cursor[i] = run;
        run += g_deg[i];
    }
    if (t == SCAN_T - 1) g_rowptr[NN] = excl + s;
}
__global__ void __launch_bounds__(256) scatter_kernel(const int* __restrict__ ei)
{
    int i = blockIdx.x * 256 + threadIdx.x;
    if (i < NE) {
        int dst = ei[NE + i];
        int pos = atomicAdd(&g_cursor[dst], 1);
        g_adj[pos] = make_int2(ei[i], i);
    }
}

// ================= misc clears =================
__global__ void __launch_bounds__(512) clear_stats_kernel() { g_stats[threadIdx.x] = 0.f; }
__global__ void __launch_bounds__(256) clear_pool_kernel()
{
    int i = blockIdx.x * 256 + threadIdx.x;
    if (i < NG * HID) g_pool[i] = 0.f;
    if (i < NG) g_cnt[i] = 0.f;
}

// ================= weight prep =================
__global__ void __launch_bounds__(256) convert_w_kernel(
    const float* __restrict__ Wq, const float* __restrict__ Wk,
    const float* __restrict__ Wv, const float* __restrict__ Wskip)
{
    int idx = blockIdx.x * 256 + threadIdx.x;
    int k = idx & 255;
    int n = (idx >> 8) & 255;
    int w = (idx >> 16) & 3;
    int l = idx >> 18;
    const float* W = (w == 0) ? Wq : (w == 1) ? Wk : (w == 2) ? Wv : Wskip;
    float val = W[((size_t)l * 256 + k) * 256 + n];
    __nv_bfloat16 hi = __float2bfloat16(val);
    __nv_bfloat16 lo = __float2bfloat16(val - __bfloat162float(hi));
    g_whi[idx] = hi;
    g_wlo[idx] = lo;
}

// ================= initial x prep =================
__global__ void __launch_bounds__(256) convert_x_kernel()
{
    size_t idx = (size_t)blockIdx.x * 256 + threadIdx.x;
    int r = (int)(idx >> 8);
    float val = (r < NN) ? g_x[idx] : 0.f;
    __nv_bfloat16 hi = __float2bfloat16(val);
    __nv_bfloat16 lo = __float2bfloat16(val - __bfloat162float(hi));
    g_ahi[idx] = hi;
    g_alo[idx] = lo;
}

// ================= mma.sync bf16 GEMM =================
#define APAD 72
#define ASMEM_ELEMS (128 * APAD)
#define BSMEM_ELEMS (256 * APAD)

__device__ __forceinline__ void mma16816(float* c, const uint32_t* a, uint32_t b0, uint32_t b1) {
    asm volatile("mma.sync.aligned.m16n8k16.row.col.f32.bf16.bf16.f32 "
                 "{%0,%1,%2,%3}, {%4,%5,%6,%7}, {%8,%9}, {%0,%1,%2,%3};"
                 : "+f"(c[0]), "+f"(c[1]), "+f"(c[2]), "+f"(c[3])
                 : "r"(a[0]), "r"(a[1]), "r"(a[2]), "r"(a[3]), "r"(b0), "r"(b1));
}

__global__ void __launch_bounds__(256, 1) mmagemm_kernel(
    int l, const float* __restrict__ b0p, const float* __restrict__ b1p,
    const float* __restrict__ b2p, const float* __restrict__ b3p)
{
    extern __shared__ __align__(16) __nv_bfloat16 sm[];
    __nv_bfloat16* sA = sm;
    __nv_bfloat16* sB = sm + ASMEM_ELEMS;

    const int tid  = threadIdx.x;
    const int lane = tid & 31;
    const int wid  = tid >> 5;
    const int gid  = lane >> 2;
    const int tig  = lane & 3;
    const int rt   = blockIdx.x;
    const int w    = blockIdx.y;
    const int m0   = (wid >> 2) * 64;
    const int n0   = (wid & 3) * 64;

    float acc[4][8][4];
#pragma unroll
    for (int i = 0; i < 4; i++)
#pragma unroll
        for (int j = 0; j < 8; j++)
#pragma unroll
            for (int t = 0; t < 4; t++) acc[i][j][t] = 0.f;

    const size_t aoff = (size_t)rt * 128 * HID;
    const size_t boff = (size_t)(l * 4 + w) * HID * HID;

#pragma unroll 1
    for (int pass = 0; pass < 3; pass++) {
        const __nv_bfloat16* Ag = ((pass == 1) ? g_alo : g_ahi) + aoff;
        const __nv_bfloat16* Bg = ((pass == 2) ? g_wlo : g_whi) + boff;
#pragma unroll 1
        for (int kt = 0; kt < 4; kt++) {
            const int kbase = kt * 64;
            __syncthreads();
#pragma unroll
            for (int it = 0; it < 4; it++) {
                int e = tid + it * 256;
                int row = e >> 3, kg = e & 7;
                uint4 v = *(const uint4*)(Ag + (size_t)row * HID + kbase + kg * 8);
                *(uint4*)(sA + row * APAD + kg * 8) = v;
            }
#pragma unroll
            for (int it = 0; it < 8; it++) {
                int e = tid + it * 256;
                int row = e >> 3, kg = e & 7;
                uint4 v = *(const uint4*)(Bg + (size_t)row * HID + kbase + kg * 8);
                *(uint4*)(sB + row * APAD + kg * 8) = v;
            }
            __syncthreads();

#pragma unroll
            for (int kk = 0; kk < 4; kk++) {
                const int k0 = kk * 16;
                uint32_t af[4][4];
#pragma unroll
                for (int i = 0; i < 4; i++) {
                    const __nv_bfloat16* base = sA + (m0 + i * 16 + gid) * APAD + k0 + 2 * tig;
                    af[i][0] = *(const uint32_t*)(base);
                    af[i][1] = *(const uint32_t*)(base + 8 * APAD);
                    af[i][2] = *(const uint32_t*)(base + 8);
                    af[i][3] = *(const uint32_t*)(base + 8 * APAD + 8);
                }
#pragma unroll
                for (int j = 0; j < 8; j++) {
                    const __nv_bfloat16* bb = sB + (n0 + j * 8 + gid) * APAD + k0 + 2 * tig;
                    uint32_t b0 = *(const uint32_t*)(bb);
                    uint32_t b1 = *(const uint32_t*)(bb + 8);
#pragma unroll
                    for (int i = 0; i < 4; i++)
                        mma16816(acc[i][j], af[i], b0, b1);
                }
            }
        }
    }

    const float* bias = (w == 0) ? b0p : (w == 1) ? b1p : (w == 2) ? b2p : b3p;
    float* dstbase = (w == 0) ? g_qs : (w == 1) ? g_kv : (w == 2) ? g_kv : g_qs;
    const int coff = (w == 0 || w == 1) ? 0 : 256;
#pragma unroll
    for (int i = 0; i < 4; i++) {
        int node0 = rt * 128 + m0 + i * 16 + gid;
#pragma unroll
        for (int j = 0; j < 8; j++) {
            int col = n0 + j * 8 + 2 * tig;
            float2 bv = *(const float2*)(bias + col);
            if (node0 < NN) {
                float2 st = make_float2(acc[i][j][0] + bv.x, acc[i][j][1] + bv.y);
                *(float2*)(dstbase + (size_t)node0 * 512 + coff + col) = st;
            }
            int node1 = node0 + 8;
            if (node1 < NN) {
                float2 st = make_float2(acc[i][j][2] + bv.x, acc[i][j][3] + bv.y);
                *(float2*)(dstbase + (size_t)node1 * 512 + coff + col) = st;
            }
        }
    }
}

// ---------------- fp32 GEMM (input projection only, K=64) ----------------
__global__ void __launch_bounds__(256) sgemm128(
    const float* __restrict__ A, const float* __restrict__ B,
    const float* __restrict__ bias, float* __restrict__ C,
    int M, int K, int ldb, int ldc)
{
    __shared__ __align__(16) float As[8][128];
    __shared__ __align__(16) float Bs[8][128];

    const int tid = threadIdx.x;
    const int tx = tid & 15;
    const int ty = tid >> 4;
    const int row0 = blockIdx.x * 128;
    const int col0 = blockIdx.y * 128;

    const int arow = tid >> 1;
    const int akk  = (tid & 1) * 4;
    const int brow = tid >> 5;
    const int bcol = (tid & 31) * 4;

    float acc[8][8];
#pragma unroll
    for (int i = 0; i < 8; i++)
#pragma unroll
        for (int j = 0; j < 8; j++) acc[i][j] = 0.f;

    for (int kt = 0; kt < K; kt += 8) {
        float4 av = make_float4(0.f, 0.f, 0.f, 0.f);
        int r = row0 + arow;
        if (r < M) av = *(const float4*)(A + (size_t)r * K + kt + akk);
        As[akk + 0][arow] = av.x; As[akk + 1][arow] = av.y;
        As[akk + 2][arow] = av.z; As[akk + 3][arow] = av.w;

        float4 bv = *(const float4*)(B + (size_t)(kt + brow) * ldb + col0 + bcol);
        *(float4*)(&Bs[brow][bcol]) = bv;

        __syncthreads();
#pragma unroll
        for (int k = 0; k < 8; k++) {
            float ra[8], rb[8];
            *(float4*)(ra)     = *(const float4*)(&As[k][ty * 8]);
            *(float4*)(ra + 4) = *(const float4*)(&As[k][ty * 8 + 4]);
            *(float4*)(rb)     = *(const float4*)(&Bs[k][tx * 8]);
            *(float4*)(rb + 4) = *(const float4*)(&Bs[k][tx * 8 + 4]);
#pragma unroll
            for (int i = 0; i < 8; i++)
#pragma unroll
                for (int j = 0; j < 8; j++) acc[i][j] += ra[i] * rb[j];
        }
        __syncthreads();
    }

    float bvals[8];
#pragma unroll
    for (int j = 0; j < 8; j++) bvals[j] = bias[col0 + tx * 8 + j];

#pragma unroll
    for (int i = 0; i < 8; i++) {
        int r = row0 + ty * 8 + i;
        if (r < M) {
            float v[8];
#pragma unroll
            for (int j = 0; j < 8; j++) v[j] = acc[i][j] + bvals[j];
            float* cp = C + (size_t)r * ldc + col0 + tx * 8;
            *(float4*)(cp)     = *(float4*)(v);
            *(float4*)(cp + 4) = *(float4*)(v + 4);
        }
    }
}

// ================= qe precompute (We read direct from gmem; 16KB, L1-hot) =================
__global__ void __launch_bounds__(256) qe_kernel(
    const float* __restrict__ We, const float* __restrict__ be)
{
    __shared__ float sbe[HID];
    if (threadIdx.x < HID) sbe[threadIdx.x] = be[threadIdx.x];
    __syncthreads();

    int n = blockIdx.x * 8 + (threadIdx.x >> 5);
    if (n >= NN) return;
    const int lane = threadIdx.x & 31;
    const int t = lane & 7;
    const int c0 = lane * 8;

    const float4* qp = (const float4*)(g_qs + (size_t)n * 512 + c0);
    float4 q0 = qp[0], q1 = qp[1];

    float qe0 = 0.f, qe1 = 0.f, qbe;
#pragma unroll
    for (int f = 0; f < ED; f++) {
        const float4* wp = (const float4*)(We + f * HID + c0);
        float4 w0 = wp[0], w1 = wp[1];
        float p = q0.x * w0.x + q0.y * w0.y + q0.z * w0.z + q0.w * w0.w
                + q1.x * w1.x + q1.y * w1.y + q1.z * w1.z + q1.w * w1.w;
        p += __shfl_xor_sync(0xffffffffu, p, 1, 8);
        p += __shfl_xor_sync(0xffffffffu, p, 2, 8);
        p += __shfl_xor_sync(0xffffffffu, p, 4, 8);
        if (f == 2 * t)     qe0 = p;
        if (f == 2 * t + 1) qe1 = p;
    }
    {
        const float4* bp = (const float4*)(&sbe[c0]);
        float4 b0 = bp[0], b1 = bp[1];
        float p = q0.x * b0.x + q0.y * b0.y + q0.z * b0.z + q0.w * b0.w
                + q1.x * b1.x + q1.y * b1.y + q1.z * b1.z + q1.w * b1.w;
        p += __shfl_xor_sync(0xffffffffu, p, 1, 8);
        p += __shfl_xor_sync(0xffffffffu, p, 2, 8);
        p += __shfl_xor_sync(0xffffffffu, p, 4, 8);
        qbe = p;
    }
    *(float2*)(g_qe + (size_t)n * 64 + 2 * lane) = make_float2(qe0, qe1);
    if (t == 0) g_qbe[n * NH + (lane >> 3)] = qbe;
}

// ================= fused attention (R12 winner, unchanged) =================
__global__ void __launch_bounds__(256) attn_kernel(
    const float* __restrict__ eattr, const float* __restrict__ We,
    const float* __restrict__ be, const float* __restrict__ Wb)
{
    __shared__ float sbe[HID];
    __shared__ float sWb1[HID];                    // Wb0 + Wb2
    __shared__ float sWb2[HID];                    // Wb1 - Wb2

    if (threadIdx.x < HID) {
        int c = threadIdx.x;
        sbe[c] = be[c];
        float w2 = Wb[2 * HID + c];
        sWb1[c] = Wb[c] + w2;
        sWb2[c] = Wb[HID + c] - w2;
    }
    __syncthreads();

    int n = blockIdx.x * 8 + (threadIdx.x >> 5);
    if (n >= NN) return;
    const int lane = threadIdx.x & 31;
    const int t    = lane & 7;
    const int c0   = lane * 8;

    const float4* qp = (const float4*)(g_qs + (size_t)n * 512 + c0);
    float4 q0 = qp[0], q1 = qp[1];
    float2 qe = *(const float2*)(g_qe + (size_t)n * 64 + 2 * lane);
    float qbe = g_qbe[n * NH + (lane >> 3)];

    float m = -INFINITY, d = 0.f;
    float s0 = 0.f, s1 = 0.f;
    float acc[8] = {0.f,0.f,0.f,0.f,0.f,0.f,0.f,0.f};

    const int beg = g_rowptr[n], end = g_rowptr[n + 1];
    int i = beg;

    for (; i + 2 <= end; i += 2) {
        int2 A = g_adj[i];
        int2 B = g_adj[i + 1];
        const float4* kpa = (const float4*)(g_kv + (size_t)A.x * 512 + c0);
        const float4* vpa = (const float4*)(g_kv + (size_t)A.x * 512 + 256 + c0);
        const float4* kpb = (const float4*)(g_kv + (size_t)B.x * 512 + c0);
        const float4* vpb = (const float4*)(g_kv + (size_t)B.x * 512 + 256 + c0);
        float4 ka0 = kpa[0], ka1 = kpa[1];
        float4 kb0 = kpb[0], kb1 = kpb[1];
        float4 va0 = vpa[0], va1 = vpa[1];
        float4 vb0 = vpb[0], vb1 = vpb[1];
        float2 eaA = *(const float2*)(eattr + (size_t)A.y * ED + 2 * t);
        float2 eaB = *(const float2*)(eattr + (size_t)B.y * ED + 2 * t);

        float pA = q0.x * ka0.x + q0.y * ka0.y + q0.z * ka0.z + q0.w * ka0.w
                 + q1.x * ka1.x + q1.y * ka1.y + q1.z * ka1.z + q1.w * ka1.w
                 + eaA.x * qe.x + eaA.y * qe.y;
        float pB = q0.x * kb0.x + q0.y * kb0.y + q0.z * kb0.z + q0.w * kb0.w
                 + q1.x * kb1.x + q1.y * kb1.y + q1.z * kb1.z + q1.w * kb1.w
                 + eaB.x * qe.x + eaB.y * qe.y;
        pA += __shfl_xor_sync(0xffffffffu, pA, 1, 8);
        pB += __shfl_xor_sync(0xffffffffu, pB, 1, 8);
        pA += __shfl_xor_sync(0xffffffffu, pA, 2, 8);
        pB += __shfl_xor_sync(0xffffffffu, pB, 2, 8);
        pA += __shfl_xor_sync(0xffffffffu, pA, 4, 8);
        pB += __shfl_xor_sync(0xffffffffu, pB, 4, 8);
        float alphaA = (pA + qbe) * 0.125f;
        float alphaB = (pB + qbe) * 0.125f;

        {
            float mn = fmaxf(m, alphaA);
            float sc = __expf(m - mn);
            float w  = __expf(alphaA - mn);
            d  = d  * sc + w;
            s0 = s0 * sc + w * eaA.x;
            s1 = s1 * sc + w * eaA.y;
            acc[0] = acc[0] * sc + w * va0.x;
            acc[1] = acc[1] * sc + w * va0.y;
            acc[2] = acc[2] * sc + w * va0.z;
            acc[3] = acc[3] * sc + w * va0.w;
            acc[4] = acc[4] * sc + w * va1.x;
            acc[5] = acc[5] * sc + w * va1.y;
            acc[6] = acc[6] * sc + w * va1.z;
            acc[7] = acc[7] * sc + w * va1.w;
            m = mn;
        }
        {
            float mn = fmaxf(m, alphaB);
            float sc = __expf(m - mn);
            float w  = __expf(alphaB - mn);
            d  = d  * sc + w;
            s0 = s0 * sc + w * eaB.x;
            s1 = s1 * sc + w * eaB.y;
            acc[0] = acc[0] * sc + w * vb0.x;
            acc[1] = acc[1] * sc + w * vb0.y;
            acc[2] = acc[2] * sc + w * vb0.z;
            acc[3] = acc[3] * sc + w * vb0.w;
            acc[4] = acc[4] * sc + w * vb1.x;
            acc[5] = acc[5] * sc + w * vb1.y;
            acc[6] = acc[6] * sc + w * vb1.z;
            acc[7] = acc[7] * sc + w * vb1.w;
            m = mn;
        }
    }
    if (i < end) {
        int2 A = g_adj[i];
        const float4* kpa = (const float4*)(g_kv + (size_t)A.x * 512 + c0);
        const float4* vpa = (const float4*)(g_kv + (size_t)A.x * 512 + 256 + c0);
        float4 ka0 = kpa[0], ka1 = kpa[1];
        float4 va0 = vpa[0], va1 = vpa[1];
        float2 eaA = *(const float2*)(eattr + (size_t)A.y * ED + 2 * t);

        float pA = q0.x * ka0.x + q0.y * ka0.y + q0.z * ka0.z + q0.w * ka0.w
                 + q1.x * ka1.x + q1.y * ka1.y + q1.z * ka1.z + q1.w * ka1.w
                 + eaA.x * qe.x + eaA.y * qe.y;
        pA += __shfl_xor_sync(0xffffffffu, pA, 1, 8);
        pA += __shfl_xor_sync(0xffffffffu, pA, 2, 8);
        pA += __shfl_xor_sync(0xffffffffu, pA, 4, 8);
        float alphaA = (pA + qbe) * 0.125f;

        float mn = fmaxf(m, alphaA);
        float sc = __expf(m - mn);
        float w  = __expf(alphaA - mn);
        d  = d  * sc + w;
        s0 = s0 * sc + w * eaA.x;
        s1 = s1 * sc + w * eaA.y;
        acc[0] = acc[0] * sc + w * va0.x;
        acc[1] = acc[1] * sc + w * va0.y;
        acc[2] = acc[2] * sc + w * va0.z;
        acc[3] = acc[3] * sc + w * va0.w;
        acc[4] = acc[4] * sc + w * va1.x;
        acc[5] = acc[5] * sc + w * va1.y;
        acc[6] = acc[6] * sc + w * va1.z;
        acc[7] = acc[7] * sc + w * va1.w;
        m = mn;
    }

    // epilogue: out = (acc + We^T s16 + d*be) / d   (We direct from gmem)
    float o[8];
#pragma unroll
    for (int j = 0; j < 8; j++) o[j] = acc[j];
#pragma unroll
    for (int f = 0; f < ED; f++) {
        float sv = __shfl_sync(0xffffffffu, (f & 1) ? s1 : s0, f >> 1, 8);
        const float4* wp = (const float4*)(We + f * HID + c0);
        float4 w0 = wp[0], w1 = wp[1];
        o[0] += sv * w0.x; o[1] += sv * w0.y; o[2] += sv * w0.z; o[3] += sv * w0.w;
        o[4] += sv * w1.x; o[5] += sv * w1.y; o[6] += sv * w1.z; o[7] += sv * w1.w;
    }
    {
        const float4* bp = (const float4*)(&sbe[c0]);
        float4 b0 = bp[0], b1 = bp[1];
        o[0] += d * b0.x; o[1] += d * b0.y; o[2] += d * b0.z; o[3] += d * b0.w;
        o[4] += d * b1.x; o[5] += d * b1.y; o[6] += d * b1.z; o[7] += d * b1.w;
    }
    float inv = (d > 0.f) ? (1.f / d) : 0.f;
#pragma unroll
    for (int j = 0; j < 8; j++) o[j] *= inv;

    // beta gate
    float sk[8];
    {
        const float4* sp = (const float4*)(g_qs + (size_t)n * 512 + 256 + c0);
        float4 s0v = sp[0], s1v = sp[1];
        sk[0]=s0v.x; sk[1]=s0v.y; sk[2]=s0v.z; sk[3]=s0v.w;
        sk[4]=s1v.x; sk[5]=s1v.y; sk[6]=s1v.z; sk[7]=s1v.w;
    }
    float p = 0.f;
#pragma unroll
    for (int j = 0; j < 8; j++) {
        int c = c0 + j;
        p += o[j] * sWb1[c] + sk[j] * sWb2[c];
    }
#pragma unroll
    for (int off = 16; off; off >>= 1) p += __shfl_xor_sync(0xffffffffu, p, off);
    float beta = 1.f / (1.f + __expf(-p));

    float* op = g_attn + (size_t)n * HID + c0;
    float r[8];
#pragma unroll
    for (int j = 0; j < 8; j++) r[j] = beta * sk[j] + (1.f - beta) * o[j];
    *(float4*)(op)     = *(float4*)(r);
    *(float4*)(op + 4) = *(float4*)(r + 4);
}

// ---------------- batchnorm stats ----------------
__global__ void __launch_bounds__(256) bnstats_kernel()
{
    int c = threadIdx.x;
    int r0 = blockIdx.x * 128;
    int r1 = min(r0 + 128, NN);
    float s = 0.f, s2 = 0.f;
    for (int r = r0; r < r1; r++) {
        float v = g_attn[(size_t)r * HID + c];
        s += v; s2 += v * v;
    }
    atomicAdd(&g_stats[c], s);
    atomicAdd(&g_stats[HID + c], s2);
}

// ---------------- batchnorm apply + LeakyReLU + bf16 split ----------------
__global__ void __launch_bounds__(256) bnapply_convert_kernel(
    const float* __restrict__ gamma, const float* __restrict__ bbeta, int do_convert)
{
    size_t idx = (size_t)blockIdx.x * blockDim.x + threadIdx.x;
    if (idx >= (size_t)NN * HID) return;
    int c = (int)(idx & (HID - 1));
    const float invN = 1.f / (float)NN;
    float mu = g_stats[c] * invN;
    float var = g_stats[HID + c] * invN - mu * mu;
    var = fmaxf(var, 0.f);
    float y = (g_attn[idx] - mu) * rsqrtf(var + BN_EPS) * gamma[c] + bbeta[c];
    y = (y >= 0.f) ? y : 0.1f * y;
    g_x[idx] = y;
    if (do_convert) {
        __nv_bfloat16 hi = __float2bfloat16(y);
        __nv_bfloat16 lo = __float2bfloat16(y - __bfloat162float(hi));
        g_ahi[idx] = hi;
        g_alo[idx] = lo;
    }
}

// ---------------- pooling ----------------
__global__ void __launch_bounds__(256) pool_kernel(const int* __restrict__ batch)
{
    int c = threadIdx.x;
    int r0 = blockIdx.x * 128;
    if (r0 >= NN) return;
    int r1 = min(r0 + 128, NN);
    int cur = batch[r0];
    float s = 0.f;
    int run = 0;
    for (int r = r0; r < r1; r++) {
        int b = batch[r];
        if (b != cur) {
            atomicAdd(&g_pool[cur * HID + c], s);
            if (c == 0) atomicAdd(&g_cnt[cur], (float)run);
            s = 0.f; run = 0; cur = b;
        }
        s += g_x[(size_t)r * HID + c];
        run++;
    }
    atomicAdd(&g_pool[cur * HID + c], s);
    if (c == 0) atomicAdd(&g_cnt[cur], (float)run);
}

// ---------------- head ----------------
__global__ void __launch_bounds__(256) head_kernel(
    const float* __restrict__ hW, const float* __restrict__ hb,
    float* __restrict__ out)
{
    __shared__ float red[8];
    int g = blockIdx.x;
    int c = threadIdx.x;
    float s = g_pool[g * HID + c];
    float ct = fmaxf(g_cnt[g], 1.f);
    float p = (s / ct) * hW[c] + s * hW[HID + c];
#pragma unroll
    for (int off = 16; off; off >>= 1) p += __shfl_xor_sync(0xffffffffu, p, off);
    if ((c & 31) == 0) red[c >> 5] = p;
    __syncthreads();
    if (c == 0) {
        float t = 0.f;
#pragma unroll
        for (int i = 0; i < 8; i++) t += red[i];
        out[g] = t + hb[0];
    }
}

// ---------------- host ----------------
#define GEMM_SMEM_BYTES ((128 * 72 + 256 * 72) * 2)

extern "C" void kernel_launch(void* const* d_in, const int* in_sizes, int n_in,
                              void* d_out, int out_size)
{
    const float* node_features = (const float*)d_in[0];
    const int*   edge_index    = (const int*)d_in[1];
    const float* edge_attr     = (const float*)d_in[2];
    const int*   batch         = (const int*)d_in[3];
    const float* proj_W        = (const float*)d_in[4];
    const float* proj_b        = (const float*)d_in[5];
    const float* Wq            = (const float*)d_in[6];
    const float* bq            = (const float*)d_in[7];
    const float* Wk            = (const float*)d_in[8];
    const float* bk            = (const float*)d_in[9];
    const float* Wv            = (const float*)d_in[10];
    const float* bv            = (const float*)d_in[11];
    const float* We            = (const float*)d_in[12];
    const float* be            = (const float*)d_in[13];
    const float* Wskip         = (const float*)d_in[14];
    const float* bskip         = (const float*)d_in[15];
    const float* Wbeta         = (const float*)d_in[16];
    const float* bng           = (const float*)d_in[17];
    const float* bnb           = (const float*)d_in[18];
    const float* headW         = (const float*)d_in[19];
    const float* headb         = (const float*)d_in[20];
    float* out = (float*)d_out;

    cudaFuncSetAttribute(mmagemm_kernel, cudaFuncAttributeMaxDynamicSharedMemorySize, GEMM_SMEM_BYTES);

    float* px;
    cudaGetSymbolAddress((void**)&px, g_x);

    // CSR by dst + weight prep (layer-invariant)
    clear_deg_kernel<<<(NN + 255) / 256, 256>>>();
    hist_kernel<<<(NE + 255) / 256, 256>>>(edge_index);
    scan_kernel<<<1, SCAN_T>>>();
    scatter_kernel<<<(NE + 255) / 256, 256>>>(edge_index);
    convert_w_kernel<<<(NL * 4 * 256 * 256) / 256, 256>>>(Wq, Wk, Wv, Wskip);

    // input projection (fp32 FFMA; K=64)
    dim3 gNode((NN + 127) / 128, 2);
    sgemm128<<<gNode, 256>>>(node_features, proj_W, proj_b, px, NN, IND, HID, HID);
    convert_x_kernel<<<(PAD_ROWS * 256) / 256, 256>>>();

    for (int l = 0; l < NL; l++) {
        clear_stats_kernel<<<1, 512>>>();
        mmagemm_kernel<<<dim3(RT_TILES, 4), 256, GEMM_SMEM_BYTES>>>(
            l, bq + l * HID, bk + l * HID, bv + l * HID, bskip + l * HID);
        qe_kernel<<<(NN + 7) / 8, 256>>>(We + (size_t)l * ED * HID, be + l * HID);
        attn_kernel<<<(NN + 7) / 8, 256>>>(edge_attr,
                                           We + (size_t)l * ED * HID,
                                           be + l * HID,
                                           Wbeta + (size_t)l * 3 * HID);
        bnstats_kernel<<<(NN + 127) / 128, 256>>>();
        bnapply_convert_kernel<<<(NN * HID + 255) / 256, 256>>>(
            bng + l * HID, bnb + l * HID, (l < NL - 1) ? 1 : 0);
    }

    clear_pool_kernel<<<(NG * HID + 255) / 256, 256>>>();
    pool_kernel<<<(NN + 127) / 128, 256>>>(batch);
    head_kernel<<<NG, 256>>>(headW, headb, out);
}